// round 3
// baseline (speedup 1.0000x reference)
#include <cuda_runtime.h>
#include <cstdint>

#define N_NODES 50000
#define IN_DIM  256
#define HID     128
#define OUT_DIM 64

// Scratch (device globals: allocation-free rule)
__device__ float g_h[(size_t)N_NODES * HID];     // node features (current layer)
__device__ float g_agg[(size_t)N_NODES * HID];   // segment-sum accumulator
__device__ float g_s1[N_NODES];                  // per-node dot with att_w[:H]
__device__ float g_s2[N_NODES];                  // per-node dot with att_w[H:]
__device__ int   g_is64;                         // 1 if edge_index is int64

// ---------------------------------------------------------------------------
// dtype probe: view edge buffer as int32. If true dtype is int64 (values
// < 50000 => high word always 0), all odd positions are 0. If int32, odd
// positions are random node ids -> virtually impossible to be all zero.
// ---------------------------------------------------------------------------
__global__ void detect_dtype_kernel(const int* __restrict__ ei32, int n32) {
    int allzero = 1;
    for (int k = 0; k < 128; k++) {
        int idx = 1 + (int)(((long long)k * (n32 - 2)) / 128);
        idx |= 1;  // odd position
        if (ei32[idx] != 0) { allzero = 0; break; }
    }
    g_is64 = allzero;
}

// ---------------------------------------------------------------------------
// GEMM0: g_h = relu(x @ W0 + b0).  x:[N,256], W0:[256,128] row-major.
// ---------------------------------------------------------------------------
#define G0_ROWS 8
__global__ void __launch_bounds__(128) gemm0_kernel(const float* __restrict__ x,
                                                    const float* __restrict__ W0,
                                                    const float* __restrict__ b0) {
    __shared__ float xs[G0_ROWS * IN_DIM];   // 8 KB
    const int tid  = threadIdx.x;            // 0..127 = output column
    const int row0 = blockIdx.x * G0_ROWS;

    const float* xsrc = x + (size_t)row0 * IN_DIM;
    #pragma unroll
    for (int i = 0; i < G0_ROWS * IN_DIM / 128; i++)
        xs[tid + i * 128] = xsrc[tid + i * 128];
    __syncthreads();

    float acc[G0_ROWS];
    #pragma unroll
    for (int r = 0; r < G0_ROWS; r++) acc[r] = 0.f;

    #pragma unroll 8
    for (int k = 0; k < IN_DIM; k++) {
        const float w = W0[k * HID + tid];
        #pragma unroll
        for (int r = 0; r < G0_ROWS; r++)
            acc[r] = fmaf(xs[r * IN_DIM + k], w, acc[r]);
    }

    const float bias = b0[tid];
    #pragma unroll
    for (int r = 0; r < G0_ROWS; r++) {
        float v = acc[r] + bias;
        g_h[(size_t)(row0 + r) * HID + tid] = v > 0.f ? v : 0.f;
    }
}

// ---------------------------------------------------------------------------
// node_prep: per node compute s1 = h·w1, s2 = h·w2 and zero agg row.
// One warp per node. att_w: [256] (first 128 = w1, last 128 = w2).
// ---------------------------------------------------------------------------
__global__ void __launch_bounds__(256) node_prep_kernel(const float* __restrict__ att_w) {
    const int warp = (blockIdx.x * blockDim.x + threadIdx.x) >> 5;
    if (warp >= N_NODES) return;
    const int lane = threadIdx.x & 31;

    const float4* hrow = (const float4*)(g_h + (size_t)warp * HID);
    float4 v = hrow[lane];
    const float4 w1 = ((const float4*)att_w)[lane];
    const float4 w2 = ((const float4*)(att_w + HID))[lane];

    float s1 = v.x * w1.x + v.y * w1.y + v.z * w1.z + v.w * w1.w;
    float s2 = v.x * w2.x + v.y * w2.y + v.z * w2.z + v.w * w2.w;
    #pragma unroll
    for (int off = 16; off > 0; off >>= 1) {
        s1 += __shfl_down_sync(0xffffffffu, s1, off);
        s2 += __shfl_down_sync(0xffffffffu, s2, off);
    }
    if (lane == 0) { g_s1[warp] = s1; g_s2[warp] = s2; }

    ((float4*)(g_agg + (size_t)warp * HID))[lane] = make_float4(0.f, 0.f, 0.f, 0.f);
}

// ---------------------------------------------------------------------------
// edge kernel: one warp per edge.
//   alpha = tanh(s1[row] + s2[col] + b);  scatter-add (alpha * h[row]) into agg[col]
// ---------------------------------------------------------------------------
__global__ void __launch_bounds__(256) edge_kernel(const int* __restrict__ ei32,
                                                   const float* __restrict__ att_b,
                                                   int E) {
    const int e = (blockIdx.x * blockDim.x + threadIdx.x) >> 5;
    if (e >= E) return;
    const int lane = threadIdx.x & 31;

    int row, col;
    if (g_is64) {        // int64 layout: low words at even int32 positions
        row = ei32[2 * e];
        col = ei32[2 * (E + e)];
    } else {             // int32 layout
        row = ei32[e];
        col = ei32[E + e];
    }
    if ((unsigned)row >= N_NODES || (unsigned)col >= N_NODES) return;

    const float alpha = tanhf(g_s1[row] + g_s2[col] + att_b[0]);

    float4 v = ((const float4*)(g_h + (size_t)row * HID))[lane];

    float* dst = g_agg + (size_t)col * HID + lane * 4;
    atomicAdd(dst + 0, alpha * v.x);
    atomicAdd(dst + 1, alpha * v.y);
    atomicAdd(dst + 2, alpha * v.z);
    atomicAdd(dst + 3, alpha * v.w);
}

// ---------------------------------------------------------------------------
// update_mid: h = relu(eps*h + (1-eps)*agg); compute next-layer s1/s2; zero agg.
// ---------------------------------------------------------------------------
__global__ void __launch_bounds__(256) update_mid_kernel(const float* __restrict__ eps_p,
                                                         const float* __restrict__ att_w_next) {
    const int warp = (blockIdx.x * blockDim.x + threadIdx.x) >> 5;
    if (warp >= N_NODES) return;
    const int lane = threadIdx.x & 31;
    const float eps = eps_p[0];
    const float ome = 1.f - eps;

    float4* hrow = (float4*)(g_h + (size_t)warp * HID);
    float4* arow = (float4*)(g_agg + (size_t)warp * HID);
    float4 h = hrow[lane];
    float4 a = arow[lane];
    h.x = fmaf(eps, h.x, ome * a.x); h.x = h.x > 0.f ? h.x : 0.f;
    h.y = fmaf(eps, h.y, ome * a.y); h.y = h.y > 0.f ? h.y : 0.f;
    h.z = fmaf(eps, h.z, ome * a.z); h.z = h.z > 0.f ? h.z : 0.f;
    h.w = fmaf(eps, h.w, ome * a.w); h.w = h.w > 0.f ? h.w : 0.f;
    hrow[lane] = h;
    arow[lane] = make_float4(0.f, 0.f, 0.f, 0.f);

    const float4 w1 = ((const float4*)att_w_next)[lane];
    const float4 w2 = ((const float4*)(att_w_next + HID))[lane];
    float s1 = h.x * w1.x + h.y * w1.y + h.z * w1.z + h.w * w1.w;
    float s2 = h.x * w2.x + h.y * w2.y + h.z * w2.z + h.w * w2.w;
    #pragma unroll
    for (int off = 16; off > 0; off >>= 1) {
        s1 += __shfl_down_sync(0xffffffffu, s1, off);
        s2 += __shfl_down_sync(0xffffffffu, s2, off);
    }
    if (lane == 0) { g_s1[warp] = s1; g_s2[warp] = s2; }
}

// ---------------------------------------------------------------------------
// update_final: h = relu(eps*h + (1-eps)*agg) only.
// ---------------------------------------------------------------------------
__global__ void __launch_bounds__(256) update_final_kernel(const float* __restrict__ eps_p) {
    const int warp = (blockIdx.x * blockDim.x + threadIdx.x) >> 5;
    if (warp >= N_NODES) return;
    const int lane = threadIdx.x & 31;
    const float eps = eps_p[0];
    const float ome = 1.f - eps;

    float4* hrow = (float4*)(g_h + (size_t)warp * HID);
    float4 h = hrow[lane];
    float4 a = ((const float4*)(g_agg + (size_t)warp * HID))[lane];
    h.x = fmaf(eps, h.x, ome * a.x); h.x = h.x > 0.f ? h.x : 0.f;
    h.y = fmaf(eps, h.y, ome * a.y); h.y = h.y > 0.f ? h.y : 0.f;
    h.z = fmaf(eps, h.z, ome * a.z); h.z = h.z > 0.f ? h.z : 0.f;
    h.w = fmaf(eps, h.w, ome * a.w); h.w = h.w > 0.f ? h.w : 0.f;
    hrow[lane] = h;
}

// ---------------------------------------------------------------------------
// GEMMC: out = g_h @ Wc + bc.  g_h:[N,128], Wc:[128,64].
// ---------------------------------------------------------------------------
#define GC_ROWS 8
__global__ void __launch_bounds__(64) gemmc_kernel(const float* __restrict__ Wc,
                                                   const float* __restrict__ bc,
                                                   float* __restrict__ out) {
    __shared__ float hs[GC_ROWS * HID];  // 4 KB
    const int tid  = threadIdx.x;         // 0..63 = output col
    const int row0 = blockIdx.x * GC_ROWS;

    const float* hsrc = g_h + (size_t)row0 * HID;
    #pragma unroll
    for (int i = 0; i < GC_ROWS * HID / 64; i++)
        hs[tid + i * 64] = hsrc[tid + i * 64];
    __syncthreads();

    float acc[GC_ROWS];
    #pragma unroll
    for (int r = 0; r < GC_ROWS; r++) acc[r] = 0.f;

    #pragma unroll 8
    for (int k = 0; k < HID; k++) {
        const float w = Wc[k * OUT_DIM + tid];
        #pragma unroll
        for (int r = 0; r < GC_ROWS; r++)
            acc[r] = fmaf(hs[r * HID + k], w, acc[r]);
    }

    const float bias = bc[tid];
    #pragma unroll
    for (int r = 0; r < GC_ROWS; r++)
        out[(size_t)(row0 + r) * OUT_DIM + tid] = acc[r] + bias;
}

// ---------------------------------------------------------------------------
extern "C" void kernel_launch(void* const* d_in, const int* in_sizes, int n_in,
                              void* d_out, int out_size) {
    const float* x    = (const float*)d_in[0];
    const int*   ei32 = (const int*)d_in[1];
    const float* W0   = (const float*)d_in[2];
    const float* b0   = (const float*)d_in[3];
    const float* aw1  = (const float*)d_in[4];
    const float* ab1  = (const float*)d_in[5];
    const float* eps1 = (const float*)d_in[6];
    const float* aw2  = (const float*)d_in[7];
    const float* ab2  = (const float*)d_in[8];
    const float* eps2 = (const float*)d_in[9];
    const float* Wc   = (const float*)d_in[10];
    const float* bc   = (const float*)d_in[11];
    float*       out  = (float*)d_out;

    const int E = in_sizes[1] / 2;   // edge_index is [2, E]; element count same for i32/i64

    const int node_warp_blocks = (N_NODES + 7) / 8;   // 256 thr = 8 warps/block
    const int edge_blocks      = (E + 7) / 8;

    detect_dtype_kernel<<<1, 1>>>(ei32, in_sizes[1]);
    gemm0_kernel<<<N_NODES / G0_ROWS, 128>>>(x, W0, b0);
    node_prep_kernel<<<node_warp_blocks, 256>>>(aw1);
    edge_kernel<<<edge_blocks, 256>>>(ei32, ab1, E);
    update_mid_kernel<<<node_warp_blocks, 256>>>(eps1, aw2);
    edge_kernel<<<edge_blocks, 256>>>(ei32, ab2, E);
    update_final_kernel<<<node_warp_blocks, 256>>>(eps2);
    gemmc_kernel<<<N_NODES / GC_ROWS, 64>>>(Wc, bc, out);
}

// round 4
// speedup vs baseline: 1.7701x; 1.7701x over previous
#include <cuda_runtime.h>
#include <cstdint>

#define N_NODES 50000
#define IN_DIM  256
#define HID     128
#define OUT_DIM 64

// Scratch (device globals: allocation-free rule)
__device__ float g_h[(size_t)N_NODES * HID];     // node features (current layer)
__device__ float g_agg[(size_t)N_NODES * HID];   // segment-sum accumulator
__device__ float g_s1[N_NODES];                  // per-node dot with att_w[:H]
__device__ float g_s2[N_NODES];                  // per-node dot with att_w[H:] (+ bias)
__device__ int   g_is64;                         // 1 if edge_index is int64

// ---- f32x2 helpers (packed dual-FMA; ptxas never auto-fuses, must use PTX) ----
__device__ __forceinline__ unsigned long long pack2(float lo, float hi) {
    unsigned long long p;
    asm("mov.b64 %0, {%1, %2};" : "=l"(p) : "f"(lo), "f"(hi));
    return p;
}
__device__ __forceinline__ void unpack2(unsigned long long p, float& lo, float& hi) {
    asm("mov.b64 {%0, %1}, %2;" : "=f"(lo), "=f"(hi) : "l"(p));
}
__device__ __forceinline__ void fma2(unsigned long long& d, unsigned long long a,
                                     unsigned long long b) {
    asm("fma.rn.f32x2 %0, %1, %2, %0;" : "+l"(d) : "l"(a), "l"(b));
}

// ---------------------------------------------------------------------------
// dtype probe: view edge buffer as int32. int64 node ids < 50000 have all-zero
// high words at odd int32 positions; int32 layout has random ids there.
// ---------------------------------------------------------------------------
__global__ void detect_dtype_kernel(const int* __restrict__ ei32, int n32) {
    int allzero = 1;
    for (int k = 0; k < 128; k++) {
        int idx = 1 + (int)(((long long)k * (n32 - 2)) / 128);
        idx |= 1;
        if (ei32[idx] != 0) { allzero = 0; break; }
    }
    g_is64 = allzero;
}

// ---------------------------------------------------------------------------
// GEMM0: g_h = relu(x @ W0 + b0).  x:[N,256], W0:[256,128] row-major.
// 128 threads (1 per col), 16 rows/block, f32x2 packed row-pair accumulators.
// smem tile transposed & padded: xs[k*18 + r], r = 0..15 (pairs 8B-aligned).
// ---------------------------------------------------------------------------
#define G0_ROWS 16
#define G0_PAD  18
__global__ void __launch_bounds__(128) gemm0_kernel(const float* __restrict__ x,
                                                    const float* __restrict__ W0,
                                                    const float* __restrict__ b0) {
    __shared__ float xs[IN_DIM * G0_PAD];     // 18 KB
    const int tid  = threadIdx.x;             // output column
    const int row0 = blockIdx.x * G0_ROWS;

    // load x tile transposed: idx = row*256+col (coalesced read)
    const float* xsrc = x + (size_t)row0 * IN_DIM;
    #pragma unroll
    for (int i = 0; i < G0_ROWS * IN_DIM / 128; i++) {
        int idx = tid + i * 128;
        int row = idx >> 8;      // /256
        int col = idx & 255;
        xs[col * G0_PAD + row] = xsrc[idx];
    }
    __syncthreads();

    unsigned long long acc[G0_ROWS / 2];
    #pragma unroll
    for (int r = 0; r < G0_ROWS / 2; r++) acc[r] = 0ull;

    #pragma unroll 4
    for (int k = 0; k < IN_DIM; k++) {
        const float w = W0[k * HID + tid];
        const unsigned long long w2 = pack2(w, w);
        const unsigned long long* xp =
            (const unsigned long long*)(xs + k * G0_PAD);
        #pragma unroll
        for (int rp = 0; rp < G0_ROWS / 2; rp++)
            fma2(acc[rp], xp[rp], w2);
    }

    const float bias = b0[tid];
    #pragma unroll
    for (int rp = 0; rp < G0_ROWS / 2; rp++) {
        float lo, hi;
        unpack2(acc[rp], lo, hi);
        lo += bias; hi += bias;
        lo = lo > 0.f ? lo : 0.f;
        hi = hi > 0.f ? hi : 0.f;
        g_h[(size_t)(row0 + 2 * rp)     * HID + tid] = lo;
        g_h[(size_t)(row0 + 2 * rp + 1) * HID + tid] = hi;
    }
}

// ---------------------------------------------------------------------------
// node_prep: s1 = h·w1, s2 = h·w2 + bias; zero agg row. One warp per node.
// ---------------------------------------------------------------------------
__global__ void __launch_bounds__(256) node_prep_kernel(const float* __restrict__ att_w,
                                                        const float* __restrict__ att_b) {
    const int warp = (blockIdx.x * blockDim.x + threadIdx.x) >> 5;
    if (warp >= N_NODES) return;
    const int lane = threadIdx.x & 31;

    const float4 v  = ((const float4*)(g_h + (size_t)warp * HID))[lane];
    const float4 w1 = ((const float4*)att_w)[lane];
    const float4 w2 = ((const float4*)(att_w + HID))[lane];

    float s1 = v.x * w1.x + v.y * w1.y + v.z * w1.z + v.w * w1.w;
    float s2 = v.x * w2.x + v.y * w2.y + v.z * w2.z + v.w * w2.w;
    #pragma unroll
    for (int off = 16; off > 0; off >>= 1) {
        s1 += __shfl_down_sync(0xffffffffu, s1, off);
        s2 += __shfl_down_sync(0xffffffffu, s2, off);
    }
    if (lane == 0) { g_s1[warp] = s1; g_s2[warp] = s2 + att_b[0]; }

    ((float4*)(g_agg + (size_t)warp * HID))[lane] = make_float4(0.f, 0.f, 0.f, 0.f);
}

// ---------------------------------------------------------------------------
// edge kernel: one warp per edge.
//   alpha = tanh(s1[row] + s2b[col]);  red.v4 (alpha*h[row]) -> agg[col]
// ---------------------------------------------------------------------------
__global__ void __launch_bounds__(256) edge_kernel(const int* __restrict__ ei32, int E) {
    const int e = (blockIdx.x * blockDim.x + threadIdx.x) >> 5;
    if (e >= E) return;
    const int lane = threadIdx.x & 31;

    int row, col;
    if (g_is64) {        // int64: low words at even int32 positions
        row = ei32[2 * e];
        col = ei32[2 * (E + e)];
    } else {
        row = ei32[e];
        col = ei32[E + e];
    }
    if ((unsigned)row >= N_NODES || (unsigned)col >= N_NODES) return;

    const float alpha = tanhf(g_s1[row] + g_s2[col]);

    float4 v = ((const float4*)(g_h + (size_t)row * HID))[lane];
    v.x *= alpha; v.y *= alpha; v.z *= alpha; v.w *= alpha;

    float* dst = g_agg + (size_t)col * HID + lane * 4;
    asm volatile("red.global.add.v4.f32 [%0], {%1,%2,%3,%4};"
                 :: "l"(dst), "f"(v.x), "f"(v.y), "f"(v.z), "f"(v.w)
                 : "memory");
}

// ---------------------------------------------------------------------------
// update_mid: h = relu(eps*h + (1-eps)*agg); next-layer s1/s2(+bias); zero agg.
// ---------------------------------------------------------------------------
__global__ void __launch_bounds__(256) update_mid_kernel(const float* __restrict__ eps_p,
                                                         const float* __restrict__ att_w_next,
                                                         const float* __restrict__ att_b_next) {
    const int warp = (blockIdx.x * blockDim.x + threadIdx.x) >> 5;
    if (warp >= N_NODES) return;
    const int lane = threadIdx.x & 31;
    const float eps = eps_p[0];
    const float ome = 1.f - eps;

    float4* hrow = (float4*)(g_h + (size_t)warp * HID);
    float4* arow = (float4*)(g_agg + (size_t)warp * HID);
    float4 h = hrow[lane];
    float4 a = arow[lane];
    h.x = fmaf(eps, h.x, ome * a.x); h.x = h.x > 0.f ? h.x : 0.f;
    h.y = fmaf(eps, h.y, ome * a.y); h.y = h.y > 0.f ? h.y : 0.f;
    h.z = fmaf(eps, h.z, ome * a.z); h.z = h.z > 0.f ? h.z : 0.f;
    h.w = fmaf(eps, h.w, ome * a.w); h.w = h.w > 0.f ? h.w : 0.f;
    hrow[lane] = h;
    arow[lane] = make_float4(0.f, 0.f, 0.f, 0.f);

    const float4 w1 = ((const float4*)att_w_next)[lane];
    const float4 w2 = ((const float4*)(att_w_next + HID))[lane];
    float s1 = h.x * w1.x + h.y * w1.y + h.z * w1.z + h.w * w1.w;
    float s2 = h.x * w2.x + h.y * w2.y + h.z * w2.z + h.w * w2.w;
    #pragma unroll
    for (int off = 16; off > 0; off >>= 1) {
        s1 += __shfl_down_sync(0xffffffffu, s1, off);
        s2 += __shfl_down_sync(0xffffffffu, s2, off);
    }
    if (lane == 0) { g_s1[warp] = s1; g_s2[warp] = s2 + att_b_next[0]; }
}

// ---------------------------------------------------------------------------
// GEMMC fused with final update:
//   hv = relu(eps*h + (1-eps)*agg);  out = hv @ Wc + bc
// 64 threads (1 per col), 16 rows/block, f32x2 packed.
// smem transposed & padded: hs[k*18 + r].
// ---------------------------------------------------------------------------
#define GC_ROWS 16
#define GC_PAD  18
__global__ void __launch_bounds__(64) gemmc_kernel(const float* __restrict__ Wc,
                                                   const float* __restrict__ bc,
                                                   const float* __restrict__ eps_p,
                                                   float* __restrict__ out) {
    __shared__ float hs[HID * GC_PAD];   // 9 KB
    const int tid  = threadIdx.x;         // output column (0..63)
    const int row0 = blockIdx.x * GC_ROWS;
    const float eps = eps_p[0];
    const float ome = 1.f - eps;

    const float* hsrc = g_h   + (size_t)row0 * HID;
    const float* asrc = g_agg + (size_t)row0 * HID;
    #pragma unroll
    for (int i = 0; i < GC_ROWS * HID / 64; i++) {
        int idx = tid + i * 64;
        int row = idx >> 7;      // /128
        int col = idx & 127;
        float v = fmaf(eps, hsrc[idx], ome * asrc[idx]);
        hs[col * GC_PAD + row] = v > 0.f ? v : 0.f;
    }
    __syncthreads();

    unsigned long long acc[GC_ROWS / 2];
    #pragma unroll
    for (int r = 0; r < GC_ROWS / 2; r++) acc[r] = 0ull;

    #pragma unroll 4
    for (int k = 0; k < HID; k++) {
        const float w = Wc[k * OUT_DIM + tid];
        const unsigned long long w2 = pack2(w, w);
        const unsigned long long* hp =
            (const unsigned long long*)(hs + k * GC_PAD);
        #pragma unroll
        for (int rp = 0; rp < GC_ROWS / 2; rp++)
            fma2(acc[rp], hp[rp], w2);
    }

    const float bias = bc[tid];
    #pragma unroll
    for (int rp = 0; rp < GC_ROWS / 2; rp++) {
        float lo, hi;
        unpack2(acc[rp], lo, hi);
        out[(size_t)(row0 + 2 * rp)     * OUT_DIM + tid] = lo + bias;
        out[(size_t)(row0 + 2 * rp + 1) * OUT_DIM + tid] = hi + bias;
    }
}

// ---------------------------------------------------------------------------
extern "C" void kernel_launch(void* const* d_in, const int* in_sizes, int n_in,
                              void* d_out, int out_size) {
    const float* x    = (const float*)d_in[0];
    const int*   ei32 = (const int*)d_in[1];
    const float* W0   = (const float*)d_in[2];
    const float* b0   = (const float*)d_in[3];
    const float* aw1  = (const float*)d_in[4];
    const float* ab1  = (const float*)d_in[5];
    const float* eps1 = (const float*)d_in[6];
    const float* aw2  = (const float*)d_in[7];
    const float* ab2  = (const float*)d_in[8];
    const float* eps2 = (const float*)d_in[9];
    const float* Wc   = (const float*)d_in[10];
    const float* bc   = (const float*)d_in[11];
    float*       out  = (float*)d_out;

    const int E = in_sizes[1] / 2;

    const int node_warp_blocks = (N_NODES + 7) / 8;
    const int edge_blocks      = (E + 7) / 8;

    detect_dtype_kernel<<<1, 1>>>(ei32, in_sizes[1]);
    gemm0_kernel<<<N_NODES / G0_ROWS, 128>>>(x, W0, b0);         // 3125 blocks
    node_prep_kernel<<<node_warp_blocks, 256>>>(aw1, ab1);
    edge_kernel<<<edge_blocks, 256>>>(ei32, E);
    update_mid_kernel<<<node_warp_blocks, 256>>>(eps1, aw2, ab2);
    edge_kernel<<<edge_blocks, 256>>>(ei32, E);
    gemmc_kernel<<<N_NODES / GC_ROWS, 64>>>(Wc, bc, eps2, out);  // 3125 blocks
}

// round 5
// speedup vs baseline: 2.4120x; 1.3626x over previous
#include <cuda_runtime.h>
#include <cstdint>

#define N_NODES 50000
#define IN_DIM  256
#define HID     128
#define OUT_DIM 64
#define E_MAX   800000

// Scratch (device globals: allocation-free rule)
__device__ float g_h[(size_t)N_NODES * HID];     // node features (current layer)
__device__ float g_agg[(size_t)N_NODES * HID];   // segment-sum result
__device__ float g_s1[N_NODES];                  // per-node dot with att_w[:H]
__device__ float g_s2[N_NODES];                  // per-node dot with att_w[H:] (+ bias)
__device__ int   g_is64;                         // 1 if edge_index is int64
// CSR build
__device__ int g_deg[N_NODES];                   // in-degree histogram
__device__ int g_rowptr[N_NODES + 1];            // exclusive prefix (by dst)
__device__ int g_cursor[N_NODES];                // scatter cursors
__device__ int g_bsum[64];                       // per-block scan totals
__device__ int g_boff[64];                       // scanned block offsets
__device__ int g_src_sorted[E_MAX];              // src node id, sorted by dst

// ---- f32x2 helpers ----
__device__ __forceinline__ unsigned long long pack2(float lo, float hi) {
    unsigned long long p;
    asm("mov.b64 %0, {%1, %2};" : "=l"(p) : "f"(lo), "f"(hi));
    return p;
}
__device__ __forceinline__ void unpack2(unsigned long long p, float& lo, float& hi) {
    asm("mov.b64 {%0, %1}, %2;" : "=f"(lo), "=f"(hi) : "l"(p));
}
__device__ __forceinline__ void fma2(unsigned long long& d, unsigned long long a,
                                     unsigned long long b) {
    asm("fma.rn.f32x2 %0, %1, %2, %0;" : "+l"(d) : "l"(a), "l"(b));
}

// ---- edge index fetch (dtype-agnostic) ----
__device__ __forceinline__ int edge_row(const int* ei32, int e, int E) {
    return g_is64 ? ei32[2 * e] : ei32[e];
}
__device__ __forceinline__ int edge_col(const int* ei32, int e, int E) {
    return g_is64 ? ei32[2 * (E + e)] : ei32[E + e];
}

// ---------------------------------------------------------------------------
// dtype probe: int64 node ids < 50000 have all-zero high words at odd int32
// positions; int32 layout has random node ids there.
// ---------------------------------------------------------------------------
__global__ void detect_dtype_kernel(const int* __restrict__ ei32, int n32) {
    int allzero = 1;
    for (int k = 0; k < 128; k++) {
        int idx = 1 + (int)(((long long)k * (n32 - 2)) / 128);
        idx |= 1;
        if (ei32[idx] != 0) { allzero = 0; break; }
    }
    g_is64 = allzero;
}

// ---------------------------------------------------------------------------
// CSR build: zero -> histogram -> scan(3 stages) -> scatter
// ---------------------------------------------------------------------------
__global__ void zero_deg_kernel() {
    int i = blockIdx.x * blockDim.x + threadIdx.x;
    if (i < N_NODES) g_deg[i] = 0;
}

__global__ void hist_kernel(const int* __restrict__ ei32, int E) {
    int e = blockIdx.x * blockDim.x + threadIdx.x;
    if (e >= E) return;
    int col = edge_col(ei32, e, E);
    if ((unsigned)col < N_NODES) atomicAdd(&g_deg[col], 1);
}

// stage 1: per-1024-block exclusive scan; block totals to g_bsum
__global__ void __launch_bounds__(1024) scan_partial_kernel(int n) {
    __shared__ int wsum[32];
    const int tid = threadIdx.x;
    const int gid = blockIdx.x * 1024 + tid;
    const int lane = tid & 31, wid = tid >> 5;

    int v = (gid < n) ? g_deg[gid] : 0;
    int inc = v;
    #pragma unroll
    for (int o = 1; o < 32; o <<= 1) {
        int t = __shfl_up_sync(0xffffffffu, inc, o);
        if (lane >= o) inc += t;
    }
    if (lane == 31) wsum[wid] = inc;
    __syncthreads();
    if (tid < 32) {
        int w = wsum[tid];
        int wi = w;
        #pragma unroll
        for (int o = 1; o < 32; o <<= 1) {
            int t = __shfl_up_sync(0xffffffffu, wi, o);
            if (tid >= o) wi += t;
        }
        wsum[tid] = wi - w;   // exclusive warp offsets
    }
    __syncthreads();
    int exc = inc - v + wsum[wid];
    if (gid < n) g_rowptr[gid] = exc;
    if (tid == 1023) g_bsum[blockIdx.x] = exc + v;   // block total
}

// stage 2: scan block totals (nblocks <= 64) with one warp, 2 elems/lane
__global__ void scan_spine_kernel(int nblocks) {
    const int lane = threadIdx.x;
    int v0 = (2 * lane     < nblocks) ? g_bsum[2 * lane]     : 0;
    int v1 = (2 * lane + 1 < nblocks) ? g_bsum[2 * lane + 1] : 0;
    int t = v0 + v1;
    int inc = t;
    #pragma unroll
    for (int o = 1; o < 32; o <<= 1) {
        int u = __shfl_up_sync(0xffffffffu, inc, o);
        if (lane >= o) inc += u;
    }
    int exc = inc - t;
    if (2 * lane     < nblocks) g_boff[2 * lane]     = exc;
    if (2 * lane + 1 < nblocks) g_boff[2 * lane + 1] = exc + v0;
}

// stage 3: add block offsets; init cursor; set rowptr[N]=E
__global__ void __launch_bounds__(1024) scan_fixup_kernel(int n, int E) {
    const int gid = blockIdx.x * 1024 + threadIdx.x;
    if (gid < n) {
        int v = g_rowptr[gid] + g_boff[blockIdx.x];
        g_rowptr[gid] = v;
        g_cursor[gid] = v;
    }
    if (gid == 0) g_rowptr[n] = E;
}

__global__ void scatter_kernel(const int* __restrict__ ei32, int E) {
    int e = blockIdx.x * blockDim.x + threadIdx.x;
    if (e >= E) return;
    int row = edge_row(ei32, e, E);
    int col = edge_col(ei32, e, E);
    if ((unsigned)row >= N_NODES || (unsigned)col >= N_NODES) return;
    int pos = atomicAdd(&g_cursor[col], 1);
    g_src_sorted[pos] = row;
}

// ---------------------------------------------------------------------------
// GEMM0: g_h = relu(x @ W0 + b0).  f32x2, 128 thr (1/col), 16 rows/block.
// ---------------------------------------------------------------------------
#define G0_ROWS 16
#define G0_PAD  18
__global__ void __launch_bounds__(128) gemm0_kernel(const float* __restrict__ x,
                                                    const float* __restrict__ W0,
                                                    const float* __restrict__ b0) {
    __shared__ float xs[IN_DIM * G0_PAD];     // 18 KB
    const int tid  = threadIdx.x;
    const int row0 = blockIdx.x * G0_ROWS;

    const float* xsrc = x + (size_t)row0 * IN_DIM;
    #pragma unroll
    for (int i = 0; i < G0_ROWS * IN_DIM / 128; i++) {
        int idx = tid + i * 128;
        xs[(idx & 255) * G0_PAD + (idx >> 8)] = xsrc[idx];
    }
    __syncthreads();

    unsigned long long acc[G0_ROWS / 2];
    #pragma unroll
    for (int r = 0; r < G0_ROWS / 2; r++) acc[r] = 0ull;

    #pragma unroll 4
    for (int k = 0; k < IN_DIM; k++) {
        const float w = W0[k * HID + tid];
        const unsigned long long w2 = pack2(w, w);
        const unsigned long long* xp = (const unsigned long long*)(xs + k * G0_PAD);
        #pragma unroll
        for (int rp = 0; rp < G0_ROWS / 2; rp++) fma2(acc[rp], xp[rp], w2);
    }

    const float bias = b0[tid];
    #pragma unroll
    for (int rp = 0; rp < G0_ROWS / 2; rp++) {
        float lo, hi;
        unpack2(acc[rp], lo, hi);
        lo += bias; hi += bias;
        g_h[(size_t)(row0 + 2 * rp)     * HID + tid] = lo > 0.f ? lo : 0.f;
        g_h[(size_t)(row0 + 2 * rp + 1) * HID + tid] = hi > 0.f ? hi : 0.f;
    }
}

// ---------------------------------------------------------------------------
// node_prep: s1 = h·w1, s2 = h·w2 + bias. One warp per node.
// ---------------------------------------------------------------------------
__global__ void __launch_bounds__(256) node_prep_kernel(const float* __restrict__ att_w,
                                                        const float* __restrict__ att_b) {
    const int warp = (blockIdx.x * blockDim.x + threadIdx.x) >> 5;
    if (warp >= N_NODES) return;
    const int lane = threadIdx.x & 31;

    const float4 v  = ((const float4*)(g_h + (size_t)warp * HID))[lane];
    const float4 w1 = ((const float4*)att_w)[lane];
    const float4 w2 = ((const float4*)(att_w + HID))[lane];

    float s1 = v.x * w1.x + v.y * w1.y + v.z * w1.z + v.w * w1.w;
    float s2 = v.x * w2.x + v.y * w2.y + v.z * w2.z + v.w * w2.w;
    #pragma unroll
    for (int off = 16; off > 0; off >>= 1) {
        s1 += __shfl_down_sync(0xffffffffu, s1, off);
        s2 += __shfl_down_sync(0xffffffffu, s2, off);
    }
    if (lane == 0) { g_s1[warp] = s1; g_s2[warp] = s2 + att_b[0]; }
}

// ---------------------------------------------------------------------------
// agg kernel (CSR): one warp per destination node. No atomics.
//   acc = sum_{e in in(d)} tanh(s1[src]+s2b[d]) * h[src];  g_agg[d] = acc
// ---------------------------------------------------------------------------
__global__ void __launch_bounds__(256) agg_kernel() {
    const int d = (blockIdx.x * blockDim.x + threadIdx.x) >> 5;
    if (d >= N_NODES) return;
    const int lane = threadIdx.x & 31;

    const float s2b = g_s2[d];
    const int start = g_rowptr[d];
    const int end   = g_rowptr[d + 1];

    float4 acc = make_float4(0.f, 0.f, 0.f, 0.f);
    for (int e = start; e < end; e++) {
        const int src = g_src_sorted[e];
        const float alpha = tanhf(g_s1[src] + s2b);
        const float4 v = ((const float4*)(g_h + (size_t)src * HID))[lane];
        acc.x = fmaf(alpha, v.x, acc.x);
        acc.y = fmaf(alpha, v.y, acc.y);
        acc.z = fmaf(alpha, v.z, acc.z);
        acc.w = fmaf(alpha, v.w, acc.w);
    }
    ((float4*)(g_agg + (size_t)d * HID))[lane] = acc;
}

// ---------------------------------------------------------------------------
// update_mid: h = relu(eps*h + (1-eps)*agg); next-layer s1/s2(+bias).
// ---------------------------------------------------------------------------
__global__ void __launch_bounds__(256) update_mid_kernel(const float* __restrict__ eps_p,
                                                         const float* __restrict__ att_w_next,
                                                         const float* __restrict__ att_b_next) {
    const int warp = (blockIdx.x * blockDim.x + threadIdx.x) >> 5;
    if (warp >= N_NODES) return;
    const int lane = threadIdx.x & 31;
    const float eps = eps_p[0];
    const float ome = 1.f - eps;

    float4* hrow = (float4*)(g_h + (size_t)warp * HID);
    float4 h = hrow[lane];
    float4 a = ((const float4*)(g_agg + (size_t)warp * HID))[lane];
    h.x = fmaf(eps, h.x, ome * a.x); h.x = h.x > 0.f ? h.x : 0.f;
    h.y = fmaf(eps, h.y, ome * a.y); h.y = h.y > 0.f ? h.y : 0.f;
    h.z = fmaf(eps, h.z, ome * a.z); h.z = h.z > 0.f ? h.z : 0.f;
    h.w = fmaf(eps, h.w, ome * a.w); h.w = h.w > 0.f ? h.w : 0.f;
    hrow[lane] = h;

    const float4 w1 = ((const float4*)att_w_next)[lane];
    const float4 w2 = ((const float4*)(att_w_next + HID))[lane];
    float s1 = h.x * w1.x + h.y * w1.y + h.z * w1.z + h.w * w1.w;
    float s2 = h.x * w2.x + h.y * w2.y + h.z * w2.z + h.w * w2.w;
    #pragma unroll
    for (int off = 16; off > 0; off >>= 1) {
        s1 += __shfl_down_sync(0xffffffffu, s1, off);
        s2 += __shfl_down_sync(0xffffffffu, s2, off);
    }
    if (lane == 0) { g_s1[warp] = s1; g_s2[warp] = s2 + att_b_next[0]; }
}

// ---------------------------------------------------------------------------
// GEMMC fused with final update: hv = relu(eps*h+(1-eps)*agg); out = hv@Wc+bc
// ---------------------------------------------------------------------------
#define GC_ROWS 16
#define GC_PAD  18
__global__ void __launch_bounds__(64) gemmc_kernel(const float* __restrict__ Wc,
                                                   const float* __restrict__ bc,
                                                   const float* __restrict__ eps_p,
                                                   float* __restrict__ out) {
    __shared__ float hs[HID * GC_PAD];   // 9 KB
    const int tid  = threadIdx.x;
    const int row0 = blockIdx.x * GC_ROWS;
    const float eps = eps_p[0];
    const float ome = 1.f - eps;

    const float* hsrc = g_h   + (size_t)row0 * HID;
    const float* asrc = g_agg + (size_t)row0 * HID;
    #pragma unroll
    for (int i = 0; i < GC_ROWS * HID / 64; i++) {
        int idx = tid + i * 64;
        float v = fmaf(eps, hsrc[idx], ome * asrc[idx]);
        hs[(idx & 127) * GC_PAD + (idx >> 7)] = v > 0.f ? v : 0.f;
    }
    __syncthreads();

    unsigned long long acc[GC_ROWS / 2];
    #pragma unroll
    for (int r = 0; r < GC_ROWS / 2; r++) acc[r] = 0ull;

    #pragma unroll 4
    for (int k = 0; k < HID; k++) {
        const float w = Wc[k * OUT_DIM + tid];
        const unsigned long long w2 = pack2(w, w);
        const unsigned long long* hp = (const unsigned long long*)(hs + k * GC_PAD);
        #pragma unroll
        for (int rp = 0; rp < GC_ROWS / 2; rp++) fma2(acc[rp], hp[rp], w2);
    }

    const float bias = bc[tid];
    #pragma unroll
    for (int rp = 0; rp < GC_ROWS / 2; rp++) {
        float lo, hi;
        unpack2(acc[rp], lo, hi);
        out[(size_t)(row0 + 2 * rp)     * OUT_DIM + tid] = lo + bias;
        out[(size_t)(row0 + 2 * rp + 1) * OUT_DIM + tid] = hi + bias;
    }
}

// ---------------------------------------------------------------------------
extern "C" void kernel_launch(void* const* d_in, const int* in_sizes, int n_in,
                              void* d_out, int out_size) {
    const float* x    = (const float*)d_in[0];
    const int*   ei32 = (const int*)d_in[1];
    const float* W0   = (const float*)d_in[2];
    const float* b0   = (const float*)d_in[3];
    const float* aw1  = (const float*)d_in[4];
    const float* ab1  = (const float*)d_in[5];
    const float* eps1 = (const float*)d_in[6];
    const float* aw2  = (const float*)d_in[7];
    const float* ab2  = (const float*)d_in[8];
    const float* eps2 = (const float*)d_in[9];
    const float* Wc   = (const float*)d_in[10];
    const float* bc   = (const float*)d_in[11];
    float*       out  = (float*)d_out;

    const int E = in_sizes[1] / 2;

    const int node_warp_blocks = (N_NODES + 7) / 8;       // 256 thr = 8 warps
    const int scan_blocks = (N_NODES + 1023) / 1024;      // 49

    detect_dtype_kernel<<<1, 1>>>(ei32, in_sizes[1]);
    // CSR build (interleave with gemm0 for overlap via stream order anyway)
    zero_deg_kernel<<<(N_NODES + 255) / 256, 256>>>();
    hist_kernel<<<(E + 255) / 256, 256>>>(ei32, E);
    scan_partial_kernel<<<scan_blocks, 1024>>>(N_NODES);
    scan_spine_kernel<<<1, 32>>>(scan_blocks);
    scan_fixup_kernel<<<scan_blocks, 1024>>>(N_NODES, E);
    scatter_kernel<<<(E + 255) / 256, 256>>>(ei32, E);

    gemm0_kernel<<<N_NODES / G0_ROWS, 128>>>(x, W0, b0);
    node_prep_kernel<<<node_warp_blocks, 256>>>(aw1, ab1);
    agg_kernel<<<node_warp_blocks, 256>>>();
    update_mid_kernel<<<node_warp_blocks, 256>>>(eps1, aw2, ab2);
    agg_kernel<<<node_warp_blocks, 256>>>();
    gemmc_kernel<<<N_NODES / GC_ROWS, 64>>>(Wc, bc, eps2, out);
}

// round 6
// speedup vs baseline: 2.4957x; 1.0347x over previous
#include <cuda_runtime.h>
#include <cstdint>

#define N_NODES 50000
#define IN_DIM  256
#define HID     128
#define OUT_DIM 64
#define E_MAX   800000

// Scratch (device globals: allocation-free rule)
__device__ float g_h  [(size_t)N_NODES * HID];   // feature buffer A
__device__ float g_h2 [(size_t)N_NODES * HID];   // feature buffer B (ping-pong)
__device__ float g_s1a[N_NODES], g_s2a[N_NODES]; // layer-1 attention dots
__device__ float g_s1b[N_NODES], g_s2b[N_NODES]; // layer-2 attention dots
__device__ int   g_is64;
// CSR build
__device__ int g_deg[N_NODES];
__device__ int g_rowptr[N_NODES + 1];
__device__ int g_cursor[N_NODES];
__device__ int g_bsum[64];
__device__ int g_boff[64];
__device__ int g_src_sorted[E_MAX];

// ---- f32x2 helpers ----
__device__ __forceinline__ unsigned long long pack2(float lo, float hi) {
    unsigned long long p;
    asm("mov.b64 %0, {%1, %2};" : "=l"(p) : "f"(lo), "f"(hi));
    return p;
}
__device__ __forceinline__ void unpack2(unsigned long long p, float& lo, float& hi) {
    asm("mov.b64 {%0, %1}, %2;" : "=f"(lo), "=f"(hi) : "l"(p));
}
__device__ __forceinline__ void fma2(unsigned long long& d, unsigned long long a,
                                     unsigned long long b) {
    asm("fma.rn.f32x2 %0, %1, %2, %0;" : "+l"(d) : "l"(a), "l"(b));
}

// ---- edge index fetch (dtype-agnostic) ----
__device__ __forceinline__ int edge_row(const int* ei32, int e, int E) {
    return g_is64 ? ei32[2 * e] : ei32[e];
}
__device__ __forceinline__ int edge_col(const int* ei32, int e, int E) {
    return g_is64 ? ei32[2 * (E + e)] : ei32[E + e];
}

// ---------------------------------------------------------------------------
// dtype probe (parallel): int64 node ids < 50000 => all-zero high words at odd
// int32 positions. 128 threads sample, ballot, thread 0 writes.
// ---------------------------------------------------------------------------
__global__ void detect_dtype_kernel(const int* __restrict__ ei32, int n32) {
    const int t = threadIdx.x;    // 0..127
    int idx = (1 + (int)(((long long)t * (n32 - 2)) / 128)) | 1;
    int nz = (ei32[idx] != 0) ? 1 : 0;
    __shared__ int any;
    if (t == 0) any = 0;
    __syncthreads();
    if (__syncthreads_or(nz)) { if (t == 0) g_is64 = 0; }
    else                      { if (t == 0) g_is64 = 1; }
}

// ---------------------------------------------------------------------------
// CSR build
// ---------------------------------------------------------------------------
__global__ void zero_deg_kernel() {
    int i = blockIdx.x * blockDim.x + threadIdx.x;
    if (i < N_NODES) g_deg[i] = 0;
}

__global__ void hist_kernel(const int* __restrict__ ei32, int E) {
    int e = blockIdx.x * blockDim.x + threadIdx.x;
    if (e >= E) return;
    int col = edge_col(ei32, e, E);
    if ((unsigned)col < N_NODES) atomicAdd(&g_deg[col], 1);
}

__global__ void __launch_bounds__(1024) scan_partial_kernel(int n) {
    __shared__ int wsum[32];
    const int tid = threadIdx.x;
    const int gid = blockIdx.x * 1024 + tid;
    const int lane = tid & 31, wid = tid >> 5;

    int v = (gid < n) ? g_deg[gid] : 0;
    int inc = v;
    #pragma unroll
    for (int o = 1; o < 32; o <<= 1) {
        int t = __shfl_up_sync(0xffffffffu, inc, o);
        if (lane >= o) inc += t;
    }
    if (lane == 31) wsum[wid] = inc;
    __syncthreads();
    if (tid < 32) {
        int w = wsum[tid];
        int wi = w;
        #pragma unroll
        for (int o = 1; o < 32; o <<= 1) {
            int t = __shfl_up_sync(0xffffffffu, wi, o);
            if (tid >= o) wi += t;
        }
        wsum[tid] = wi - w;
    }
    __syncthreads();
    int exc = inc - v + wsum[wid];
    if (gid < n) g_rowptr[gid] = exc;
    if (tid == 1023) g_bsum[blockIdx.x] = exc + v;
}

__global__ void scan_spine_kernel(int nblocks) {
    const int lane = threadIdx.x;
    int v0 = (2 * lane     < nblocks) ? g_bsum[2 * lane]     : 0;
    int v1 = (2 * lane + 1 < nblocks) ? g_bsum[2 * lane + 1] : 0;
    int t = v0 + v1;
    int inc = t;
    #pragma unroll
    for (int o = 1; o < 32; o <<= 1) {
        int u = __shfl_up_sync(0xffffffffu, inc, o);
        if (lane >= o) inc += u;
    }
    int exc = inc - t;
    if (2 * lane     < nblocks) g_boff[2 * lane]     = exc;
    if (2 * lane + 1 < nblocks) g_boff[2 * lane + 1] = exc + v0;
}

__global__ void __launch_bounds__(1024) scan_fixup_kernel(int n, int E) {
    const int gid = blockIdx.x * 1024 + threadIdx.x;
    if (gid < n) {
        int v = g_rowptr[gid] + g_boff[blockIdx.x];
        g_rowptr[gid] = v;
        g_cursor[gid] = v;
    }
    if (gid == 0) g_rowptr[n] = E;
}

__global__ void scatter_kernel(const int* __restrict__ ei32, int E) {
    int e = blockIdx.x * blockDim.x + threadIdx.x;
    if (e >= E) return;
    int row = edge_row(ei32, e, E);
    int col = edge_col(ei32, e, E);
    if ((unsigned)row >= N_NODES || (unsigned)col >= N_NODES) return;
    int pos = atomicAdd(&g_cursor[col], 1);
    g_src_sorted[pos] = row;
}

// ---------------------------------------------------------------------------
// GEMM0 + fused node_prep: g_h = relu(x@W0+b0); g_s1a/g_s2a = h·w1 / h·w2+b.
// 128 thr (1/col), 16 rows/block, f32x2. smem reused for epilogue transpose.
// ---------------------------------------------------------------------------
#define G0_ROWS 16
#define G0_PAD  18
__global__ void __launch_bounds__(128) gemm0_kernel(const float* __restrict__ x,
                                                    const float* __restrict__ W0,
                                                    const float* __restrict__ b0,
                                                    const float* __restrict__ att_w,
                                                    const float* __restrict__ att_b) {
    __shared__ float xs[IN_DIM * G0_PAD];     // 18 KB; reused as hs[16*128]
    const int tid  = threadIdx.x;
    const int lane = tid & 31, wid = tid >> 5;
    const int row0 = blockIdx.x * G0_ROWS;

    const float* xsrc = x + (size_t)row0 * IN_DIM;
    #pragma unroll
    for (int i = 0; i < G0_ROWS * IN_DIM / 128; i++) {
        int idx = tid + i * 128;
        xs[(idx & 255) * G0_PAD + (idx >> 8)] = xsrc[idx];
    }
    __syncthreads();

    unsigned long long acc[G0_ROWS / 2];
    #pragma unroll
    for (int r = 0; r < G0_ROWS / 2; r++) acc[r] = 0ull;

    #pragma unroll 4
    for (int k = 0; k < IN_DIM; k++) {
        const float w = W0[k * HID + tid];
        const unsigned long long w2 = pack2(w, w);
        const unsigned long long* xp = (const unsigned long long*)(xs + k * G0_PAD);
        #pragma unroll
        for (int rp = 0; rp < G0_ROWS / 2; rp++) fma2(acc[rp], xp[rp], w2);
    }

    const float bias = b0[tid];
    float hv[G0_ROWS];
    #pragma unroll
    for (int rp = 0; rp < G0_ROWS / 2; rp++) {
        float lo, hi;
        unpack2(acc[rp], lo, hi);
        lo += bias; hi += bias;
        hv[2 * rp]     = lo > 0.f ? lo : 0.f;
        hv[2 * rp + 1] = hi > 0.f ? hi : 0.f;
        g_h[(size_t)(row0 + 2 * rp)     * HID + tid] = hv[2 * rp];
        g_h[(size_t)(row0 + 2 * rp + 1) * HID + tid] = hv[2 * rp + 1];
    }

    // epilogue: transpose h tile into smem, per-warp attention dots
    __syncthreads();                          // xs reads done
    #pragma unroll
    for (int r = 0; r < G0_ROWS; r++)
        xs[r * 128 + tid] = hv[r];
    __syncthreads();

    const float ab = att_b[0];
    #pragma unroll
    for (int r4 = 0; r4 < 4; r4++) {          // each warp: 4 rows
        const int r = wid * 4 + r4;
        const float* hr = xs + r * 128;
        float v0 = hr[lane], v1 = hr[lane + 32], v2 = hr[lane + 64], v3 = hr[lane + 96];
        float s1 = v0 * att_w[lane] + v1 * att_w[lane + 32]
                 + v2 * att_w[lane + 64] + v3 * att_w[lane + 96];
        float s2 = v0 * att_w[HID + lane] + v1 * att_w[HID + lane + 32]
                 + v2 * att_w[HID + lane + 64] + v3 * att_w[HID + lane + 96];
        #pragma unroll
        for (int off = 16; off > 0; off >>= 1) {
            s1 += __shfl_down_sync(0xffffffffu, s1, off);
            s2 += __shfl_down_sync(0xffffffffu, s2, off);
        }
        if (lane == 0) { g_s1a[row0 + r] = s1; g_s2a[row0 + r] = s2 + ab; }
    }
}

// ---------------------------------------------------------------------------
// agg kernel (CSR, no atomics): one warp per destination.
//   acc = sum tanh(s1[src]+s2b)*hsrc[src];  hnew = relu(eps*hsrc[d]+(1-eps)*acc)
//   if NEXT: also compute next-layer s1/s2 from hnew.
// alpha computed lane-parallel (1 tanh per edge), gathers 4-way unrolled (MLP).
// ---------------------------------------------------------------------------
template <bool NEXT>
__global__ void __launch_bounds__(256) agg_kernel(const float* __restrict__ hsrc,
                                                  float* __restrict__ hdst,
                                                  const float* __restrict__ s1in,
                                                  const float* __restrict__ s2in,
                                                  float* __restrict__ s1out,
                                                  float* __restrict__ s2out,
                                                  const float* __restrict__ eps_p,
                                                  const float* __restrict__ att_w,
                                                  const float* __restrict__ att_b) {
    const int d = (blockIdx.x * blockDim.x + threadIdx.x) >> 5;
    if (d >= N_NODES) return;
    const int lane = threadIdx.x & 31;

    const float s2b = s2in[d];
    const int start = g_rowptr[d];
    const int end   = g_rowptr[d + 1];

    float4 acc = make_float4(0.f, 0.f, 0.f, 0.f);
    for (int base = start; base < end; base += 32) {
        const int cnt = min(32, end - base);
        const int srcl = g_src_sorted[base + ((lane < cnt) ? lane : 0)];
        const float al = tanhf(s1in[srcl] + s2b);

        int j = 0;
        for (; j + 4 <= cnt; j += 4) {
            int s0 = __shfl_sync(0xffffffffu, srcl, j);
            int s1_ = __shfl_sync(0xffffffffu, srcl, j + 1);
            int s2_ = __shfl_sync(0xffffffffu, srcl, j + 2);
            int s3 = __shfl_sync(0xffffffffu, srcl, j + 3);
            float a0 = __shfl_sync(0xffffffffu, al, j);
            float a1 = __shfl_sync(0xffffffffu, al, j + 1);
            float a2 = __shfl_sync(0xffffffffu, al, j + 2);
            float a3 = __shfl_sync(0xffffffffu, al, j + 3);
            float4 v0 = ((const float4*)(hsrc + (size_t)s0  * HID))[lane];
            float4 v1 = ((const float4*)(hsrc + (size_t)s1_ * HID))[lane];
            float4 v2 = ((const float4*)(hsrc + (size_t)s2_ * HID))[lane];
            float4 v3 = ((const float4*)(hsrc + (size_t)s3  * HID))[lane];
            acc.x = fmaf(a0, v0.x, acc.x); acc.y = fmaf(a0, v0.y, acc.y);
            acc.z = fmaf(a0, v0.z, acc.z); acc.w = fmaf(a0, v0.w, acc.w);
            acc.x = fmaf(a1, v1.x, acc.x); acc.y = fmaf(a1, v1.y, acc.y);
            acc.z = fmaf(a1, v1.z, acc.z); acc.w = fmaf(a1, v1.w, acc.w);
            acc.x = fmaf(a2, v2.x, acc.x); acc.y = fmaf(a2, v2.y, acc.y);
            acc.z = fmaf(a2, v2.z, acc.z); acc.w = fmaf(a2, v2.w, acc.w);
            acc.x = fmaf(a3, v3.x, acc.x); acc.y = fmaf(a3, v3.y, acc.y);
            acc.z = fmaf(a3, v3.z, acc.z); acc.w = fmaf(a3, v3.w, acc.w);
        }
        for (; j < cnt; j++) {
            int s0 = __shfl_sync(0xffffffffu, srcl, j);
            float a0 = __shfl_sync(0xffffffffu, al, j);
            float4 v0 = ((const float4*)(hsrc + (size_t)s0 * HID))[lane];
            acc.x = fmaf(a0, v0.x, acc.x); acc.y = fmaf(a0, v0.y, acc.y);
            acc.z = fmaf(a0, v0.z, acc.z); acc.w = fmaf(a0, v0.w, acc.w);
        }
    }

    // epilogue: update
    const float eps = eps_p[0];
    const float ome = 1.f - eps;
    const float4 ho = ((const float4*)(hsrc + (size_t)d * HID))[lane];
    float4 hn;
    hn.x = fmaf(eps, ho.x, ome * acc.x); hn.x = hn.x > 0.f ? hn.x : 0.f;
    hn.y = fmaf(eps, ho.y, ome * acc.y); hn.y = hn.y > 0.f ? hn.y : 0.f;
    hn.z = fmaf(eps, ho.z, ome * acc.z); hn.z = hn.z > 0.f ? hn.z : 0.f;
    hn.w = fmaf(eps, ho.w, ome * acc.w); hn.w = hn.w > 0.f ? hn.w : 0.f;
    ((float4*)(hdst + (size_t)d * HID))[lane] = hn;

    if (NEXT) {
        const float4 w1 = ((const float4*)att_w)[lane];
        const float4 w2 = ((const float4*)(att_w + HID))[lane];
        float s1 = hn.x * w1.x + hn.y * w1.y + hn.z * w1.z + hn.w * w1.w;
        float s2 = hn.x * w2.x + hn.y * w2.y + hn.z * w2.z + hn.w * w2.w;
        #pragma unroll
        for (int off = 16; off > 0; off >>= 1) {
            s1 += __shfl_down_sync(0xffffffffu, s1, off);
            s2 += __shfl_down_sync(0xffffffffu, s2, off);
        }
        if (lane == 0) { s1out[d] = s1; s2out[d] = s2 + att_b[0]; }
    }
}

// ---------------------------------------------------------------------------
// GEMMC: out = g_h @ Wc + bc (h already final). f32x2, 64 thr, 16 rows/block.
// ---------------------------------------------------------------------------
#define GC_ROWS 16
#define GC_PAD  18
__global__ void __launch_bounds__(64) gemmc_kernel(const float* __restrict__ Wc,
                                                   const float* __restrict__ bc,
                                                   float* __restrict__ out) {
    __shared__ float hs[HID * GC_PAD];   // 9 KB
    const int tid  = threadIdx.x;
    const int row0 = blockIdx.x * GC_ROWS;

    const float* hsrc = g_h + (size_t)row0 * HID;
    #pragma unroll
    for (int i = 0; i < GC_ROWS * HID / 64; i++) {
        int idx = tid + i * 64;
        hs[(idx & 127) * GC_PAD + (idx >> 7)] = hsrc[idx];
    }
    __syncthreads();

    unsigned long long acc[GC_ROWS / 2];
    #pragma unroll
    for (int r = 0; r < GC_ROWS / 2; r++) acc[r] = 0ull;

    #pragma unroll 4
    for (int k = 0; k < HID; k++) {
        const float w = Wc[k * OUT_DIM + tid];
        const unsigned long long w2 = pack2(w, w);
        const unsigned long long* hp = (const unsigned long long*)(hs + k * GC_PAD);
        #pragma unroll
        for (int rp = 0; rp < GC_ROWS / 2; rp++) fma2(acc[rp], hp[rp], w2);
    }

    const float bias = bc[tid];
    #pragma unroll
    for (int rp = 0; rp < GC_ROWS / 2; rp++) {
        float lo, hi;
        unpack2(acc[rp], lo, hi);
        out[(size_t)(row0 + 2 * rp)     * OUT_DIM + tid] = lo + bias;
        out[(size_t)(row0 + 2 * rp + 1) * OUT_DIM + tid] = hi + bias;
    }
}

// ---------------------------------------------------------------------------
extern "C" void kernel_launch(void* const* d_in, const int* in_sizes, int n_in,
                              void* d_out, int out_size) {
    const float* x    = (const float*)d_in[0];
    const int*   ei32 = (const int*)d_in[1];
    const float* W0   = (const float*)d_in[2];
    const float* b0   = (const float*)d_in[3];
    const float* aw1  = (const float*)d_in[4];
    const float* ab1  = (const float*)d_in[5];
    const float* eps1 = (const float*)d_in[6];
    const float* aw2  = (const float*)d_in[7];
    const float* ab2  = (const float*)d_in[8];
    const float* eps2 = (const float*)d_in[9];
    const float* Wc   = (const float*)d_in[10];
    const float* bc   = (const float*)d_in[11];
    float*       out  = (float*)d_out;

    const int E = in_sizes[1] / 2;
    const int node_warp_blocks = (N_NODES + 7) / 8;
    const int scan_blocks = (N_NODES + 1023) / 1024;

    float* d_g_h; float* d_g_h2;
    cudaGetSymbolAddress((void**)&d_g_h,  g_h);
    cudaGetSymbolAddress((void**)&d_g_h2, g_h2);
    float *d_s1a, *d_s2a, *d_s1b, *d_s2b;
    cudaGetSymbolAddress((void**)&d_s1a, g_s1a);
    cudaGetSymbolAddress((void**)&d_s2a, g_s2a);
    cudaGetSymbolAddress((void**)&d_s1b, g_s1b);
    cudaGetSymbolAddress((void**)&d_s2b, g_s2b);

    detect_dtype_kernel<<<1, 128>>>(ei32, in_sizes[1]);
    zero_deg_kernel<<<(N_NODES + 255) / 256, 256>>>();
    hist_kernel<<<(E + 255) / 256, 256>>>(ei32, E);
    scan_partial_kernel<<<scan_blocks, 1024>>>(N_NODES);
    scan_spine_kernel<<<1, 32>>>(scan_blocks);
    scan_fixup_kernel<<<scan_blocks, 1024>>>(N_NODES, E);
    scatter_kernel<<<(E + 255) / 256, 256>>>(ei32, E);

    gemm0_kernel<<<N_NODES / G0_ROWS, 128>>>(x, W0, b0, aw1, ab1);
    agg_kernel<true ><<<node_warp_blocks, 256>>>(d_g_h,  d_g_h2, d_s1a, d_s2a,
                                                 d_s1b, d_s2b, eps1, aw2, ab2);
    agg_kernel<false><<<node_warp_blocks, 256>>>(d_g_h2, d_g_h,  d_s1b, d_s2b,
                                                 nullptr, nullptr, eps2, nullptr, nullptr);
    gemmc_kernel<<<N_NODES / GC_ROWS, 64>>>(Wc, bc, out);
}